// round 14
// baseline (speedup 1.0000x reference)
#include <cuda_runtime.h>
#include <cuda_bf16.h>

#define HW    128
#define IMG   (HW*HW)
#define BATCH 64

// Scratch buffers (allocation-free rule: __device__ globals)
__device__ float g_bufA[(size_t)BATCH * 22 * IMG];  // 22-ch concat; x lives in ch 12..21
__device__ float g_bufB[(size_t)BATCH * 24 * IMG];
__device__ float g_bufC[(size_t)BATCH * 24 * IMG];

// ---------------------------------------------------------------------------
// bf16 split helpers: f = hi + lo with hi = bf16_rn(f), lo = bf16_rn(f - hi).
// MMAs hi*hi, hi*lo, lo*hi (fp32 accum) recover ~1e-6 rel err.
// ---------------------------------------------------------------------------
__device__ __forceinline__ void split2(float f0, float f1, unsigned& hi, unsigned& lo) {
    __nv_bfloat16 h0 = __float2bfloat16(f0);
    __nv_bfloat16 h1 = __float2bfloat16(f1);
    __nv_bfloat16 l0 = __float2bfloat16(f0 - __bfloat162float(h0));
    __nv_bfloat16 l1 = __float2bfloat16(f1 - __bfloat162float(h1));
    hi = ((unsigned)__bfloat16_as_ushort(h1) << 16) | (unsigned)__bfloat16_as_ushort(h0);
    lo = ((unsigned)__bfloat16_as_ushort(l1) << 16) | (unsigned)__bfloat16_as_ushort(l0);
}

// mma.sync m16n8k8 bf16: C[16x8,f32] += A[16x8,bf16] * B[8x8,bf16]
__device__ __forceinline__ void mma_bf16(float c[4], unsigned a0, unsigned a1, unsigned b0) {
    asm("mma.sync.aligned.m16n8k8.row.col.f32.bf16.bf16.f32 "
        "{%0,%1,%2,%3}, {%4,%5}, {%6}, {%0,%1,%2,%3};"
        : "+f"(c[0]), "+f"(c[1]), "+f"(c[2]), "+f"(c[3])
        : "r"(a0), "r"(a1), "r"(b0));
}

// ---------------------------------------------------------------------------
// Per-sample 3x3 conv + eval-BN + ReLU via split-bf16 tensor-core MMA.
// CTA: 256 threads (8 warps), pixel tile 64x8 (halo 66x10, 660 records).
// R13 structure + TWO accumulator sets per (m,nb):
//   set0 <- hh term, set1 <- hl + lh terms (summed in epilogue).
// Independent HMMA chains per warp: 2m * 2sets * NBK = 8/12 (was 4/6),
// covering HMMA latency at the smem-limited occupancy.
// ---------------------------------------------------------------------------
template<int CIN, int CINP, int COUT, int COUTP>
__global__ __launch_bounds__(256, (CINP == 16) ? 3 : 2)
void conv3x3_mma(const float* __restrict__ in, int in_nch,
                 const float* __restrict__ wflat, int wP, int wbase,
                 const float* __restrict__ gam, const float* __restrict__ bet,
                 const float* __restrict__ mea, const float* __restrict__ varr,
                 int bnoff,
                 float* __restrict__ out, int out_nch)
{
    constexpr int KC   = CINP / 8;           // k-chunks of 8 channels
    constexpr int NBK  = COUTP / 8;          // n-blocks of 8 outputs
    constexpr int RSW  = (CINP == 16) ? 20 : 28;  // record stride (words)
    constexpr int CHW  = CINP / 2;           // lo-section word offset
    constexpr int TXW  = 66, TYH = 10;       // halo tile (64x8 outputs)
    constexpr int NREC = TXW * TYH;          // 660 pixel records
    constexpr int BSL  = 9 * KC * 32;        // B slots per n-block

    extern __shared__ unsigned sm[];
    unsigned* s_a = sm;                      // NREC * RSW
    unsigned* s_b = s_a + NREC * RSW;        // NBK * BSL * 2 (hi,lo interleaved)
    float*    s_sc = (float*)(s_b + 2 * NBK * BSL);
    float*    s_bi = s_sc + COUTP;

    const int tid = threadIdx.x;
    const int bS  = blockIdx.z;
    const int gx0 = blockIdx.x * 64;
    const int gy0 = blockIdx.y * 8;

    // ---- stage A: float -> (hi,lo) bf16 pair records ----
    const float* inb = in + (size_t)bS * in_nch * IMG;
    for (int u = tid; u < (CINP / 2) * NREC; u += 256) {
        int x  = u % TXW;
        int r  = u / TXW;
        int y  = r % TYH;
        int cp = r / TYH;                    // channel pair
        int gy = gy0 - 1 + y, gx = gx0 - 1 + x;
        float f0 = 0.f, f1 = 0.f;
        bool inimg = ((unsigned)gy < HW) && ((unsigned)gx < HW);
        if (inimg && 2 * cp < CIN)     f0 = inb[(size_t)(2 * cp) * IMG + gy * HW + gx];
        if (inimg && 2 * cp + 1 < CIN) f1 = inb[(size_t)(2 * cp + 1) * IMG + gy * HW + gx];
        unsigned hi, lo; split2(f0, f1, hi, lo);
        int rec = y * TXW + x;
        s_a[rec * RSW + cp]       = hi;
        s_a[rec * RSW + CHW + cp] = lo;
    }

    // ---- prep B: gmem weights -> fragment-ordered smem, (hi,lo) interleaved ----
    const float* wsrc = wflat + (size_t)bS * wP + wbase;
    for (int s = tid; s < NBK * BSL; s += 256) {
        int lane = s & 31;
        int r = s >> 5;
        int kc = r % KC;  r /= KC;
        int sh = r % 9;   r /= 9;
        int nb = r;
        int o  = nb * 8 + (lane >> 2);       // n = g
        int i0 = kc * 8 + (lane & 3) * 2;    // k = 2t, 2t+1
        float w0 = (o < COUT && i0     < CIN) ? wsrc[(o * CIN + i0    ) * 9 + sh] : 0.f;
        float w1 = (o < COUT && i0 + 1 < CIN) ? wsrc[(o * CIN + i0 + 1) * 9 + sh] : 0.f;
        unsigned hi, lo; split2(w0, w1, hi, lo);
        s_b[2 * s]     = hi;
        s_b[2 * s + 1] = lo;
    }
    if (tid < COUTP) {
        float sc = 0.f, bi = 0.f;
        if (tid < COUT) {
            int c = bnoff + tid;
            float inv = gam[c] * rsqrtf(varr[c] + 1e-5f);
            sc = inv; bi = bet[c] - mea[c] * inv;
        }
        s_sc[tid] = sc; s_bi[tid] = bi;
    }
    __syncthreads();

    const int lane = tid & 31, warp = tid >> 5;
    const int g = lane >> 2, t = lane & 3;

    const uint2* pb = (const uint2*)s_b + lane;   // + nb*BSL + q*32 (immediates)
    float* ob = out + (size_t)bS * out_nch * IMG;

    // 32 m-blocks (16 m-pairs) / 8 warps -> 2 warp-tiles per warp
    #pragma unroll 1
    for (int jj = 0; jj < 2; jj++) {
        const int mp  = warp + 8 * jj;
        const int mb0 = mp * 2, mb1 = mp * 2 + 1;
        const int base0 = ((mb0 >> 2) * TXW + (mb0 & 3) * 16 + g) * RSW + t;
        const int base1 = ((mb1 >> 2) * TXW + (mb1 & 3) * 16 + g) * RSW + t;

        float acc[2][2][NBK][4];             // [m][set][nb]; set0=hh, set1=hl+lh
        #pragma unroll
        for (int m = 0; m < 2; m++)
            #pragma unroll
            for (int e = 0; e < 2; e++)
                #pragma unroll
                for (int nb = 0; nb < NBK; nb++)
                    #pragma unroll
                    for (int i = 0; i < 4; i++) acc[m][e][nb][i] = 0.f;

        #pragma unroll
        for (int ky = 0; ky < 3; ky++)
            #pragma unroll
            for (int kx = 0; kx < 3; kx++)
                #pragma unroll
                for (int kc = 0; kc < KC; kc++) {
                    const int q   = (ky * 3 + kx) * KC + kc;
                    const int off = (ky * TXW + kx) * RSW + kc * 4;
                    // A fragments: loaded ONCE, reused by all n-blocks
                    const unsigned ah0 = s_a[base0 + off];
                    const unsigned ah1 = s_a[base0 + off + 8 * RSW];
                    const unsigned al0 = s_a[base0 + off + CHW];
                    const unsigned al1 = s_a[base0 + off + CHW + 8 * RSW];
                    const unsigned ch0 = s_a[base1 + off];
                    const unsigned ch1 = s_a[base1 + off + 8 * RSW];
                    const unsigned cl0 = s_a[base1 + off + CHW];
                    const unsigned cl1 = s_a[base1 + off + CHW + 8 * RSW];
                    // B fragments: one LDS.64 per n-block (hi,lo)
                    uint2 bb[NBK];
                    #pragma unroll
                    for (int nb = 0; nb < NBK; nb++)
                        bb[nb] = pb[nb * BSL + q * 32];
                    // hh -> set0; hl, lh -> set1 (distinct chains throughout)
                    #pragma unroll
                    for (int nb = 0; nb < NBK; nb++) {
                        mma_bf16(acc[0][0][nb], ah0, ah1, bb[nb].x);
                        mma_bf16(acc[1][0][nb], ch0, ch1, bb[nb].x);
                    }
                    #pragma unroll
                    for (int nb = 0; nb < NBK; nb++) {
                        mma_bf16(acc[0][1][nb], ah0, ah1, bb[nb].y);
                        mma_bf16(acc[1][1][nb], ch0, ch1, bb[nb].y);
                    }
                    #pragma unroll
                    for (int nb = 0; nb < NBK; nb++) {
                        mma_bf16(acc[0][1][nb], al0, al1, bb[nb].x);
                        mma_bf16(acc[1][1][nb], cl0, cl1, bb[nb].x);
                    }
                }

        // ---- epilogue: combine sets, BN (eval) + ReLU, store ----
        #pragma unroll
        for (int nb = 0; nb < NBK; nb++) {
            const int o0 = nb * 8 + 2 * t, o1 = o0 + 1;
            const float sc0 = s_sc[o0], bi0 = s_bi[o0];
            const float sc1 = s_sc[o1], bi1 = s_bi[o1];
            #pragma unroll
            for (int m = 0; m < 2; m++) {
                const int mb = mp * 2 + m;
                const int y  = gy0 + (mb >> 2);
                const int x  = gx0 + (mb & 3) * 16 + g;
                float c0 = acc[m][0][nb][0] + acc[m][1][nb][0];
                float c1 = acc[m][0][nb][1] + acc[m][1][nb][1];
                float c2 = acc[m][0][nb][2] + acc[m][1][nb][2];
                float c3 = acc[m][0][nb][3] + acc[m][1][nb][3];
                float* p = ob + (size_t)y * HW + x;
                if (o0 < COUT) {
                    p[(size_t)o0 * IMG]     = fmaxf(fmaf(c0, sc0, bi0), 0.f);
                    p[(size_t)o0 * IMG + 8] = fmaxf(fmaf(c2, sc0, bi0), 0.f);
                }
                if (o1 < COUT) {
                    p[(size_t)o1 * IMG]     = fmaxf(fmaf(c1, sc1, bi1), 0.f);
                    p[(size_t)o1 * IMG + 8] = fmaxf(fmaf(c3, sc1, bi1), 0.f);
                }
            }
        }
    }
}

// ---------------------------------------------------------------------------
// Copy x into channels 12..21 of bufA (makes the dense-skip concat free).
// ---------------------------------------------------------------------------
__global__ void copy_x_kernel(const float* __restrict__ x, float* __restrict__ bufA)
{
    size_t idx = (size_t)blockIdx.x * blockDim.x + threadIdx.x;
    const size_t total = (size_t)BATCH * 10 * IMG;
    if (idx < total) {
        int p = (int)(idx % IMG);
        int c = (int)((idx / IMG) % 10);
        int b = (int)(idx / ((size_t)IMG * 10));
        bufA[((size_t)b * 22 + 12 + c) * IMG + p] = x[idx];
    }
}

// ---------------------------------------------------------------------------
// Final per-sample 1x1 conv: [B,22,H,W] x [B,11,22] -> [B,11,H,W]
// ---------------------------------------------------------------------------
__global__ __launch_bounds__(256)
void conv1x1_kernel(const float* __restrict__ in, const float* __restrict__ w4,
                    float* __restrict__ out)
{
    __shared__ float s_w[11 * 22];
    const int b   = blockIdx.y;
    const int tid = threadIdx.x;
    if (tid < 242) s_w[tid] = w4[b * 242 + tid];
    __syncthreads();

    const int p0 = blockIdx.x * (256 * 4) + tid;
    const float* inb = in  + (size_t)b * 22 * IMG;
    float*       ob  = out + (size_t)b * 11 * IMG;

    float acc[4][11];
    #pragma unroll
    for (int q = 0; q < 4; q++)
        #pragma unroll
        for (int o = 0; o < 11; o++) acc[q][o] = 0.f;

    #pragma unroll 2
    for (int i = 0; i < 22; i++) {
        float v[4];
        #pragma unroll
        for (int q = 0; q < 4; q++) v[q] = inb[(size_t)i * IMG + p0 + q * 256];
        #pragma unroll
        for (int o = 0; o < 11; o++) {
            float w = s_w[o * 22 + i];
            #pragma unroll
            for (int q = 0; q < 4; q++) acc[q][o] = fmaf(v[q], w, acc[q][o]);
        }
    }
    #pragma unroll
    for (int o = 0; o < 11; o++)
        #pragma unroll
        for (int q = 0; q < 4; q++)
            ob[(size_t)o * IMG + p0 + q * 256] = acc[q][o];
}

// ---------------------------------------------------------------------------

static int smem_bytes_mma(int cinp, int coutp) {
    int kc  = cinp / 8, nbk = coutp / 8;
    int rsw = (cinp == 16) ? 20 : 28;
    return (660 * rsw + 2 * nbk * 9 * kc * 32 + 2 * coutp) * 4;
}

extern "C" void kernel_launch(void* const* d_in, const int* in_sizes, int n_in,
                              void* d_out, int out_size)
{
    const float* x   = (const float*)d_in[0];
    const float* w1  = (const float*)d_in[1];
    const float* w2  = (const float*)d_in[2];
    const float* w3  = (const float*)d_in[3];
    const float* w4  = (const float*)d_in[4];
    const float* gam = (const float*)d_in[5];
    const float* bet = (const float*)d_in[6];
    const float* mea = (const float*)d_in[7];
    const float* var = (const float*)d_in[8];
    float* out = (float*)d_out;

    float *bufA, *bufB, *bufC;
    cudaGetSymbolAddress((void**)&bufA, g_bufA);
    cudaGetSymbolAddress((void**)&bufB, g_bufB);
    cudaGetSymbolAddress((void**)&bufC, g_bufC);

    // opt-in to >48KB dynamic smem (idempotent; host-side, capture-safe)
    cudaFuncSetAttribute((const void*)conv3x3_mma<10,16,12,16>, cudaFuncAttributeMaxDynamicSharedMemorySize, smem_bytes_mma(16,16));
    cudaFuncSetAttribute((const void*)conv3x3_mma<12,16,12,16>, cudaFuncAttributeMaxDynamicSharedMemorySize, smem_bytes_mma(16,16));
    cudaFuncSetAttribute((const void*)conv3x3_mma<22,24,24,24>, cudaFuncAttributeMaxDynamicSharedMemorySize, smem_bytes_mma(24,24));
    cudaFuncSetAttribute((const void*)conv3x3_mma<24,24,24,24>, cudaFuncAttributeMaxDynamicSharedMemorySize, smem_bytes_mma(24,24));
    cudaFuncSetAttribute((const void*)conv3x3_mma<24,24,12,16>, cudaFuncAttributeMaxDynamicSharedMemorySize, smem_bytes_mma(24,16));

    const dim3 grd(2, 16, BATCH);   // 64x8 pixel tiles

    // x -> bufA channels 12..21 (skip-concat source, written once per launch)
    copy_x_kernel<<<(BATCH * 10 * IMG + 255) / 256, 256>>>(x, bufA);

    // ---- stage 1 ----  (BN offsets: 0,12,24)
    conv3x3_mma<10,16,12,16><<<grd, 256, smem_bytes_mma(16,16)>>>(x,    10, w1, 3672,    0, gam,bet,mea,var,   0, bufB, 24);
    conv3x3_mma<12,16,12,16><<<grd, 256, smem_bytes_mma(16,16)>>>(bufB, 24, w1, 3672, 1080, gam,bet,mea,var,  12, bufC, 24);
    conv3x3_mma<12,16,12,16><<<grd, 256, smem_bytes_mma(16,16)>>>(bufC, 24, w1, 3672, 2376, gam,bet,mea,var,  24, bufA, 22);
    // ---- stage 2 ----  (BN offsets: 36,60,84)
    conv3x3_mma<22,24,24,24><<<grd, 256, smem_bytes_mma(24,24)>>>(bufA, 22, w2, 12528,    0, gam,bet,mea,var,  36, bufB, 24);
    conv3x3_mma<24,24,24,24><<<grd, 256, smem_bytes_mma(24,24)>>>(bufB, 24, w2, 12528, 4752, gam,bet,mea,var,  60, bufC, 24);
    conv3x3_mma<24,24,12,16><<<grd, 256, smem_bytes_mma(24,16)>>>(bufC, 24, w2, 12528, 9936, gam,bet,mea,var,  84, bufA, 22);
    // ---- stage 3 ----  (BN offsets: 96,120,144)
    conv3x3_mma<22,24,24,24><<<grd, 256, smem_bytes_mma(24,24)>>>(bufA, 22, w3, 12528,    0, gam,bet,mea,var,  96, bufB, 24);
    conv3x3_mma<24,24,24,24><<<grd, 256, smem_bytes_mma(24,24)>>>(bufB, 24, w3, 12528, 4752, gam,bet,mea,var, 120, bufC, 24);
    conv3x3_mma<24,24,12,16><<<grd, 256, smem_bytes_mma(24,16)>>>(bufC, 24, w3, 12528, 9936, gam,bet,mea,var, 144, bufA, 22);
    // ---- stage 4: 1x1 predictor ----
    conv1x1_kernel<<<dim3(IMG / (256 * 4), BATCH), 256>>>(bufA, w4, out);
}

// round 15
// speedup vs baseline: 1.3979x; 1.3979x over previous
#include <cuda_runtime.h>
#include <cuda_bf16.h>

#define HW    128
#define IMG   (HW*HW)
#define BATCH 64

// Scratch buffers (allocation-free rule: __device__ globals)
__device__ float g_bufA[(size_t)BATCH * 22 * IMG];  // 22-ch concat; x lives in ch 12..21
__device__ float g_bufB[(size_t)BATCH * 24 * IMG];
__device__ float g_bufC[(size_t)BATCH * 24 * IMG];

// ---------------------------------------------------------------------------
// bf16 split helpers: f = hi + lo with hi = bf16_rn(f), lo = bf16_rn(f - hi).
// MMAs hi*hi, hi*lo, lo*hi (fp32 accum) recover ~1e-6 rel err.
// ---------------------------------------------------------------------------
__device__ __forceinline__ void split2(float f0, float f1, unsigned& hi, unsigned& lo) {
    __nv_bfloat16 h0 = __float2bfloat16(f0);
    __nv_bfloat16 h1 = __float2bfloat16(f1);
    __nv_bfloat16 l0 = __float2bfloat16(f0 - __bfloat162float(h0));
    __nv_bfloat16 l1 = __float2bfloat16(f1 - __bfloat162float(h1));
    hi = ((unsigned)__bfloat16_as_ushort(h1) << 16) | (unsigned)__bfloat16_as_ushort(h0);
    lo = ((unsigned)__bfloat16_as_ushort(l1) << 16) | (unsigned)__bfloat16_as_ushort(l0);
}

// mma m16n8k16 bf16: C[16x8] += A[16x16] * B[16x8]
__device__ __forceinline__ void mma16(float c[4], const unsigned a[4], unsigned b0, unsigned b1) {
    asm("mma.sync.aligned.m16n8k16.row.col.f32.bf16.bf16.f32 "
        "{%0,%1,%2,%3}, {%4,%5,%6,%7}, {%8,%9}, {%0,%1,%2,%3};"
        : "+f"(c[0]), "+f"(c[1]), "+f"(c[2]), "+f"(c[3])
        : "r"(a[0]), "r"(a[1]), "r"(a[2]), "r"(a[3]), "r"(b0), "r"(b1));
}
// mma m16n8k8 bf16
__device__ __forceinline__ void mma8(float c[4], unsigned a0, unsigned a1, unsigned b0) {
    asm("mma.sync.aligned.m16n8k8.row.col.f32.bf16.bf16.f32 "
        "{%0,%1,%2,%3}, {%4,%5}, {%6}, {%0,%1,%2,%3};"
        : "+f"(c[0]), "+f"(c[1]), "+f"(c[2]), "+f"(c[3])
        : "r"(a0), "r"(a1), "r"(b0));
}
// ldmatrix x4: 4 8x8 b16 matrices; lane i supplies row (i&7) of matrix (i>>3)
__device__ __forceinline__ void ldsm4(unsigned r[4], unsigned saddr) {
    asm volatile("ldmatrix.sync.aligned.m8n8.x4.shared.b16 {%0,%1,%2,%3}, [%4];"
        : "=r"(r[0]), "=r"(r[1]), "=r"(r[2]), "=r"(r[3]) : "r"(saddr));
}

// ---------------------------------------------------------------------------
// Per-sample 3x3 conv + eval-BN + ReLU via split-bf16 tensor-core MMA.
// CTA: 256 threads (8 warps), pixel tile 64x8 (halo 66x10, 660 records).
// Warp-tile: 16 px wide x 4 output rows (xseg = warp&3, y0 = (warp>>2)*4).
// Per kx: 6 input-row A fragments loaded via ldmatrix.x4 (reused across
// ky x m), B fragments via LDS.128 from fragment-ordered smem;
// m16n8k16 MMAs (+ k8 tail for CINP=24). Split-term passes:
//   pass hi: hh + hl;  pass lo: lh  -> single fused acc per (m,nb).
// ---------------------------------------------------------------------------
template<int CIN, int CINP, int COUT, int COUTP>
__global__ __launch_bounds__(256, (CINP == 16) ? 3 : 2)
void conv3x3_mma(const float* __restrict__ in, int in_nch,
                 const float* __restrict__ wflat, int wP, int wbase,
                 const float* __restrict__ gam, const float* __restrict__ bet,
                 const float* __restrict__ mea, const float* __restrict__ varr,
                 int bnoff,
                 float* __restrict__ out, int out_nch)
{
    constexpr int NBK  = COUTP / 8;          // n-blocks of 8 outputs
    constexpr int KC8  = (CINP == 24) ? 1 : 0;  // k8 tail (channels 16..23)
    constexpr int RSW  = (CINP == 16) ? 20 : 28;  // record stride (words)
    constexpr int CHW  = CINP / 2;           // lo-section word offset
    constexpr int TXW  = 66, TYH = 10;       // halo tile (64x8 outputs)
    constexpr int NREC = TXW * TYH;          // 660 pixel records

    extern __shared__ unsigned sm[];
    unsigned* s_a   = sm;                          // NREC * RSW words
    uint4*    s_b16 = (uint4*)(s_a + NREC * RSW);  // NBK*9*32 {b0h,b1h,b0l,b1l}
    uint2*    s_b8  = (uint2*)(s_b16 + NBK * 9 * 32);  // NBK*9*32 {bh,bl} (KC8)
    float*    s_sc  = (float*)(s_b8 + (KC8 ? NBK * 9 * 32 : 0));
    float*    s_bi  = s_sc + COUTP;

    const int tid = threadIdx.x;
    const int bS  = blockIdx.z;
    const int gx0 = blockIdx.x * 64;
    const int gy0 = blockIdx.y * 8;

    // ---- stage A: float -> (hi,lo) bf16 pair records ----
    const float* inb = in + (size_t)bS * in_nch * IMG;
    for (int u = tid; u < (CINP / 2) * NREC; u += 256) {
        int x  = u % TXW;
        int r  = u / TXW;
        int y  = r % TYH;
        int cp = r / TYH;                    // channel pair
        int gy = gy0 - 1 + y, gx = gx0 - 1 + x;
        float f0 = 0.f, f1 = 0.f;
        bool inimg = ((unsigned)gy < HW) && ((unsigned)gx < HW);
        if (inimg && 2 * cp < CIN)     f0 = inb[(size_t)(2 * cp) * IMG + gy * HW + gx];
        if (inimg && 2 * cp + 1 < CIN) f1 = inb[(size_t)(2 * cp + 1) * IMG + gy * HW + gx];
        unsigned hi, lo; split2(f0, f1, hi, lo);
        int rec = y * TXW + x;
        s_a[rec * RSW + cp]       = hi;
        s_a[rec * RSW + CHW + cp] = lo;
    }

    // ---- prep B (k16 chunk, channels 0..15): fragment order ----
    const float* wsrc = wflat + (size_t)bS * wP + wbase;
    for (int s = tid; s < NBK * 9 * 32; s += 256) {
        int lane = s & 31;
        int r  = s >> 5;
        int sh = r % 9;
        int nb = r / 9;
        int o  = nb * 8 + (lane >> 2);       // n = g
        int t4 = (lane & 3) * 2;             // k = t4, t4+1 (b0); t4+8.. (b1)
        float w00 = 0.f, w01 = 0.f, w10 = 0.f, w11 = 0.f;
        if (o < COUT) {
            const float* wr = wsrc + (size_t)o * CIN * 9 + sh;
            if (t4     < CIN) w00 = wr[(t4    ) * 9];
            if (t4 + 1 < CIN) w01 = wr[(t4 + 1) * 9];
            if (t4 + 8 < CIN) w10 = wr[(t4 + 8) * 9];
            if (t4 + 9 < CIN) w11 = wr[(t4 + 9) * 9];
        }
        unsigned b0h, b0l, b1h, b1l;
        split2(w00, w01, b0h, b0l);
        split2(w10, w11, b1h, b1l);
        s_b16[s] = make_uint4(b0h, b1h, b0l, b1l);
    }
    // ---- prep B (k8 tail, channels 16..23) ----
    if (KC8) {
        for (int s = tid; s < NBK * 9 * 32; s += 256) {
            int lane = s & 31;
            int r  = s >> 5;
            int sh = r % 9;
            int nb = r / 9;
            int o  = nb * 8 + (lane >> 2);
            int i0 = 16 + (lane & 3) * 2;
            float w0 = 0.f, w1 = 0.f;
            if (o < COUT) {
                const float* wr = wsrc + (size_t)o * CIN * 9 + sh;
                if (i0     < CIN) w0 = wr[(i0    ) * 9];
                if (i0 + 1 < CIN) w1 = wr[(i0 + 1) * 9];
            }
            unsigned hi, lo; split2(w0, w1, hi, lo);
            s_b8[s] = make_uint2(hi, lo);
        }
    }
    if (tid < COUTP) {
        float sc = 0.f, bi = 0.f;
        if (tid < COUT) {
            int c = bnoff + tid;
            float inv = gam[c] * rsqrtf(varr[c] + 1e-5f);
            sc = inv; bi = bet[c] - mea[c] * inv;
        }
        s_sc[tid] = sc; s_bi[tid] = bi;
    }
    __syncthreads();

    const int lane = tid & 31, warp = tid >> 5;
    const int g = lane >> 2, t = lane & 3;
    const int xseg = warp & 3;               // 16-px segment
    const int y0   = (warp >> 2) * 4;        // 4 output rows per warp

    // ldmatrix lane->address offsets (words), constant per thread:
    // matrix (lane>>3): 0=px0-7 loK, 1=px8-15 loK, 2=px0-7 hiK, 3=px8-15 hiK
    const int rowoff = ((lane >> 3) & 1) * 8 + (lane & 7);
    const int offA16 = rowoff * RSW + (lane >> 4) * 4;        // k16: words 0-3 / 4-7
    const int offA8  = rowoff * RSW + 8 + (lane >> 4) * CHW;  // k8: word 8, hi/lo split
    const unsigned sa_base = (unsigned)__cvta_generic_to_shared(s_a);

    float acc[4][NBK][4];
    #pragma unroll
    for (int m = 0; m < 4; m++)
        #pragma unroll
        for (int nb = 0; nb < NBK; nb++)
            #pragma unroll
            for (int i = 0; i < 4; i++) acc[m][nb][i] = 0.f;

    #pragma unroll
    for (int kx = 0; kx < 3; kx++) {
        const int rec0 = y0 * TXW + xseg * 16 + kx;   // input record, row-idx 0

        // ---- pass hi: A_hi rows, terms hh + hl ----
        unsigned A[6][4];
        #pragma unroll
        for (int rr = 0; rr < 6; rr++)
            ldsm4(A[rr], sa_base + ((rec0 + rr * TXW) * RSW + offA16) * 4);
        #pragma unroll
        for (int ky = 0; ky < 3; ky++)
            #pragma unroll
            for (int nb = 0; nb < NBK; nb++) {
                const uint4 B = s_b16[(nb * 9 + ky * 3 + kx) * 32 + lane];
                #pragma unroll
                for (int m = 0; m < 4; m++) mma16(acc[m][nb], A[m + ky], B.x, B.y);
                #pragma unroll
                for (int m = 0; m < 4; m++) mma16(acc[m][nb], A[m + ky], B.z, B.w);
            }

        // ---- pass lo: A_lo rows, term lh ----
        #pragma unroll
        for (int rr = 0; rr < 6; rr++)
            ldsm4(A[rr], sa_base + ((rec0 + rr * TXW) * RSW + offA16 + CHW) * 4);
        #pragma unroll
        for (int ky = 0; ky < 3; ky++)
            #pragma unroll
            for (int nb = 0; nb < NBK; nb++) {
                const uint2 Bh = *(const uint2*)&s_b16[(nb * 9 + ky * 3 + kx) * 32 + lane];
                #pragma unroll
                for (int m = 0; m < 4; m++) mma16(acc[m][nb], A[m + ky], Bh.x, Bh.y);
            }

        // ---- k8 tail (channels 16..23): hi+lo in one ldmatrix ----
        if (KC8) {
            unsigned A8[6][4];               // [0,1]=hi a0,a1; [2,3]=lo a0,a1
            #pragma unroll
            for (int rr = 0; rr < 6; rr++)
                ldsm4(A8[rr], sa_base + ((rec0 + rr * TXW) * RSW + offA8) * 4);
            #pragma unroll
            for (int ky = 0; ky < 3; ky++)
                #pragma unroll
                for (int nb = 0; nb < NBK; nb++) {
                    const uint2 B = s_b8[(nb * 9 + ky * 3 + kx) * 32 + lane];
                    #pragma unroll
                    for (int m = 0; m < 4; m++) mma8(acc[m][nb], A8[m+ky][0], A8[m+ky][1], B.x);
                    #pragma unroll
                    for (int m = 0; m < 4; m++) mma8(acc[m][nb], A8[m+ky][0], A8[m+ky][1], B.y);
                    #pragma unroll
                    for (int m = 0; m < 4; m++) mma8(acc[m][nb], A8[m+ky][2], A8[m+ky][3], B.x);
                }
        }
    }

    // ---- epilogue: BN (eval) + ReLU, store ----
    float* ob = out + (size_t)bS * out_nch * IMG;
    #pragma unroll
    for (int nb = 0; nb < NBK; nb++) {
        const int o0 = nb * 8 + 2 * t, o1 = o0 + 1;
        const float sc0 = s_sc[o0], bi0 = s_bi[o0];
        const float sc1 = s_sc[o1], bi1 = s_bi[o1];
        #pragma unroll
        for (int m = 0; m < 4; m++) {
            const int y = gy0 + y0 + m;
            const int x = gx0 + xseg * 16 + g;
            float* p = ob + (size_t)y * HW + x;
            if (o0 < COUT) {
                p[(size_t)o0 * IMG]     = fmaxf(fmaf(acc[m][nb][0], sc0, bi0), 0.f);
                p[(size_t)o0 * IMG + 8] = fmaxf(fmaf(acc[m][nb][2], sc0, bi0), 0.f);
            }
            if (o1 < COUT) {
                p[(size_t)o1 * IMG]     = fmaxf(fmaf(acc[m][nb][1], sc1, bi1), 0.f);
                p[(size_t)o1 * IMG + 8] = fmaxf(fmaf(acc[m][nb][3], sc1, bi1), 0.f);
            }
        }
    }
}

// ---------------------------------------------------------------------------
// Copy x into channels 12..21 of bufA (makes the dense-skip concat free).
// ---------------------------------------------------------------------------
__global__ void copy_x_kernel(const float* __restrict__ x, float* __restrict__ bufA)
{
    size_t idx = (size_t)blockIdx.x * blockDim.x + threadIdx.x;
    const size_t total = (size_t)BATCH * 10 * IMG;
    if (idx < total) {
        int p = (int)(idx % IMG);
        int c = (int)((idx / IMG) % 10);
        int b = (int)(idx / ((size_t)IMG * 10));
        bufA[((size_t)b * 22 + 12 + c) * IMG + p] = x[idx];
    }
}

// ---------------------------------------------------------------------------
// Final per-sample 1x1 conv: [B,22,H,W] x [B,11,22] -> [B,11,H,W]
// ---------------------------------------------------------------------------
__global__ __launch_bounds__(256)
void conv1x1_kernel(const float* __restrict__ in, const float* __restrict__ w4,
                    float* __restrict__ out)
{
    __shared__ float s_w[11 * 22];
    const int b   = blockIdx.y;
    const int tid = threadIdx.x;
    if (tid < 242) s_w[tid] = w4[b * 242 + tid];
    __syncthreads();

    const int p0 = blockIdx.x * (256 * 4) + tid;
    const float* inb = in  + (size_t)b * 22 * IMG;
    float*       ob  = out + (size_t)b * 11 * IMG;

    float acc[4][11];
    #pragma unroll
    for (int q = 0; q < 4; q++)
        #pragma unroll
        for (int o = 0; o < 11; o++) acc[q][o] = 0.f;

    #pragma unroll 2
    for (int i = 0; i < 22; i++) {
        float v[4];
        #pragma unroll
        for (int q = 0; q < 4; q++) v[q] = inb[(size_t)i * IMG + p0 + q * 256];
        #pragma unroll
        for (int o = 0; o < 11; o++) {
            float w = s_w[o * 22 + i];
            #pragma unroll
            for (int q = 0; q < 4; q++) acc[q][o] = fmaf(v[q], w, acc[q][o]);
        }
    }
    #pragma unroll
    for (int o = 0; o < 11; o++)
        #pragma unroll
        for (int q = 0; q < 4; q++)
            ob[(size_t)o * IMG + p0 + q * 256] = acc[q][o];
}

// ---------------------------------------------------------------------------

static int smem_bytes_mma(int cinp, int coutp) {
    int nbk = coutp / 8;
    int rsw = (cinp == 16) ? 20 : 28;
    int b16 = nbk * 9 * 32 * 16;
    int b8  = (cinp == 24) ? nbk * 9 * 32 * 8 : 0;
    return 660 * rsw * 4 + b16 + b8 + 2 * coutp * 4;
}

extern "C" void kernel_launch(void* const* d_in, const int* in_sizes, int n_in,
                              void* d_out, int out_size)
{
    const float* x   = (const float*)d_in[0];
    const float* w1  = (const float*)d_in[1];
    const float* w2  = (const float*)d_in[2];
    const float* w3  = (const float*)d_in[3];
    const float* w4  = (const float*)d_in[4];
    const float* gam = (const float*)d_in[5];
    const float* bet = (const float*)d_in[6];
    const float* mea = (const float*)d_in[7];
    const float* var = (const float*)d_in[8];
    float* out = (float*)d_out;

    float *bufA, *bufB, *bufC;
    cudaGetSymbolAddress((void**)&bufA, g_bufA);
    cudaGetSymbolAddress((void**)&bufB, g_bufB);
    cudaGetSymbolAddress((void**)&bufC, g_bufC);

    // opt-in to >48KB dynamic smem (idempotent; host-side, capture-safe)
    cudaFuncSetAttribute((const void*)conv3x3_mma<10,16,12,16>, cudaFuncAttributeMaxDynamicSharedMemorySize, smem_bytes_mma(16,16));
    cudaFuncSetAttribute((const void*)conv3x3_mma<12,16,12,16>, cudaFuncAttributeMaxDynamicSharedMemorySize, smem_bytes_mma(16,16));
    cudaFuncSetAttribute((const void*)conv3x3_mma<22,24,24,24>, cudaFuncAttributeMaxDynamicSharedMemorySize, smem_bytes_mma(24,24));
    cudaFuncSetAttribute((const void*)conv3x3_mma<24,24,24,24>, cudaFuncAttributeMaxDynamicSharedMemorySize, smem_bytes_mma(24,24));
    cudaFuncSetAttribute((const void*)conv3x3_mma<24,24,12,16>, cudaFuncAttributeMaxDynamicSharedMemorySize, smem_bytes_mma(24,16));

    const dim3 grd(2, 16, BATCH);   // 64x8 pixel tiles

    // x -> bufA channels 12..21 (skip-concat source, written once per launch)
    copy_x_kernel<<<(BATCH * 10 * IMG + 255) / 256, 256>>>(x, bufA);

    // ---- stage 1 ----  (BN offsets: 0,12,24)
    conv3x3_mma<10,16,12,16><<<grd, 256, smem_bytes_mma(16,16)>>>(x,    10, w1, 3672,    0, gam,bet,mea,var,   0, bufB, 24);
    conv3x3_mma<12,16,12,16><<<grd, 256, smem_bytes_mma(16,16)>>>(bufB, 24, w1, 3672, 1080, gam,bet,mea,var,  12, bufC, 24);
    conv3x3_mma<12,16,12,16><<<grd, 256, smem_bytes_mma(16,16)>>>(bufC, 24, w1, 3672, 2376, gam,bet,mea,var,  24, bufA, 22);
    // ---- stage 2 ----  (BN offsets: 36,60,84)
    conv3x3_mma<22,24,24,24><<<grd, 256, smem_bytes_mma(24,24)>>>(bufA, 22, w2, 12528,    0, gam,bet,mea,var,  36, bufB, 24);
    conv3x3_mma<24,24,24,24><<<grd, 256, smem_bytes_mma(24,24)>>>(bufB, 24, w2, 12528, 4752, gam,bet,mea,var,  60, bufC, 24);
    conv3x3_mma<24,24,12,16><<<grd, 256, smem_bytes_mma(24,16)>>>(bufC, 24, w2, 12528, 9936, gam,bet,mea,var,  84, bufA, 22);
    // ---- stage 3 ----  (BN offsets: 96,120,144)
    conv3x3_mma<22,24,24,24><<<grd, 256, smem_bytes_mma(24,24)>>>(bufA, 22, w3, 12528,    0, gam,bet,mea,var,  96, bufB, 24);
    conv3x3_mma<24,24,24,24><<<grd, 256, smem_bytes_mma(24,24)>>>(bufB, 24, w3, 12528, 4752, gam,bet,mea,var, 120, bufC, 24);
    conv3x3_mma<24,24,12,16><<<grd, 256, smem_bytes_mma(24,16)>>>(bufC, 24, w3, 12528, 9936, gam,bet,mea,var, 144, bufA, 22);
    // ---- stage 4: 1x1 predictor ----
    conv1x1_kernel<<<dim3(IMG / (256 * 4), BATCH), 256>>>(bufA, w4, out);
}

// round 16
// speedup vs baseline: 1.3991x; 1.0009x over previous
#include <cuda_runtime.h>
#include <cuda_bf16.h>

#define HW    128
#define IMG   (HW*HW)
#define BATCH 64

// Scratch buffers, PAIR-INTERLEAVED: [b][pair][pix]{c0,c1} (float2)
__device__ float2 g_bufA[(size_t)BATCH * 11 * IMG];  // 22ch; x lives in pairs 6..10
__device__ float2 g_bufB[(size_t)BATCH * 12 * IMG];
__device__ float2 g_bufC[(size_t)BATCH * 12 * IMG];

// ---------------------------------------------------------------------------
// bf16 split helpers: f = hi + lo with hi = bf16_rn(f), lo = bf16_rn(f - hi).
// MMAs hi*hi, hi*lo, lo*hi (fp32 accum) recover ~1e-6 rel err.
// ---------------------------------------------------------------------------
__device__ __forceinline__ void split2(float f0, float f1, unsigned& hi, unsigned& lo) {
    __nv_bfloat16 h0 = __float2bfloat16(f0);
    __nv_bfloat16 h1 = __float2bfloat16(f1);
    __nv_bfloat16 l0 = __float2bfloat16(f0 - __bfloat162float(h0));
    __nv_bfloat16 l1 = __float2bfloat16(f1 - __bfloat162float(h1));
    hi = ((unsigned)__bfloat16_as_ushort(h1) << 16) | (unsigned)__bfloat16_as_ushort(h0);
    lo = ((unsigned)__bfloat16_as_ushort(l1) << 16) | (unsigned)__bfloat16_as_ushort(l0);
}

// mma m16n8k16 bf16: C[16x8] += A[16x16] * B[16x8]
__device__ __forceinline__ void mma16(float c[4], const unsigned a[4], unsigned b0, unsigned b1) {
    asm("mma.sync.aligned.m16n8k16.row.col.f32.bf16.bf16.f32 "
        "{%0,%1,%2,%3}, {%4,%5,%6,%7}, {%8,%9}, {%0,%1,%2,%3};"
        : "+f"(c[0]), "+f"(c[1]), "+f"(c[2]), "+f"(c[3])
        : "r"(a[0]), "r"(a[1]), "r"(a[2]), "r"(a[3]), "r"(b0), "r"(b1));
}
// mma m16n8k8 bf16
__device__ __forceinline__ void mma8(float c[4], unsigned a0, unsigned a1, unsigned b0) {
    asm("mma.sync.aligned.m16n8k8.row.col.f32.bf16.bf16.f32 "
        "{%0,%1,%2,%3}, {%4,%5}, {%6}, {%0,%1,%2,%3};"
        : "+f"(c[0]), "+f"(c[1]), "+f"(c[2]), "+f"(c[3])
        : "r"(a0), "r"(a1), "r"(b0));
}
// ldmatrix x4: 4 8x8 b16 matrices; lane i supplies row (i&7) of matrix (i>>3)
__device__ __forceinline__ void ldsm4(unsigned r[4], unsigned saddr) {
    asm volatile("ldmatrix.sync.aligned.m8n8.x4.shared.b16 {%0,%1,%2,%3}, [%4];"
        : "=r"(r[0]), "=r"(r[1]), "=r"(r[2]), "=r"(r[3]) : "r"(saddr));
}

// ---------------------------------------------------------------------------
// Per-sample 3x3 conv + eval-BN + ReLU via split-bf16 tensor-core MMA.
// R15 hot loop unchanged (ldmatrix.x4 + m16n8k16 + k8 tail).
// NEW: pair-interleaved gmem I/O. Input (PIN=false): float2 pair records,
// one LDG.64 per (pair, pixel). Output: fragment cols (2t,2t+1) = one pair
// -> one STG.64 per pixel-half. Layer 1 (PIN=true) reads planar x.
// ---------------------------------------------------------------------------
template<int CIN, int CINP, int COUT, int COUTP, bool PIN>
__global__ __launch_bounds__(256, (CINP == 16) ? 3 : 2)
void conv3x3_mma(const void* __restrict__ in, int in_sz,   // PIN: channels, else pairs
                 const float* __restrict__ wflat, int wP, int wbase,
                 const float* __restrict__ gam, const float* __restrict__ bet,
                 const float* __restrict__ mea, const float* __restrict__ varr,
                 int bnoff,
                 float2* __restrict__ out, int out_pairs)
{
    constexpr int NBK  = COUTP / 8;          // n-blocks of 8 outputs
    constexpr int KC8  = (CINP == 24) ? 1 : 0;  // k8 tail (channels 16..23)
    constexpr int RSW  = (CINP == 16) ? 20 : 28;  // record stride (words)
    constexpr int CHW  = CINP / 2;           // lo-section word offset
    constexpr int TXW  = 66, TYH = 10;       // halo tile (64x8 outputs)
    constexpr int NREC = TXW * TYH;          // 660 pixel records

    extern __shared__ unsigned sm[];
    unsigned* s_a   = sm;                          // NREC * RSW words
    uint4*    s_b16 = (uint4*)(s_a + NREC * RSW);  // NBK*9*32 {b0h,b1h,b0l,b1l}
    uint2*    s_b8  = (uint2*)(s_b16 + NBK * 9 * 32);  // NBK*9*32 {bh,bl} (KC8)
    float*    s_sc  = (float*)(s_b8 + (KC8 ? NBK * 9 * 32 : 0));
    float*    s_bi  = s_sc + COUTP;

    const int tid = threadIdx.x;
    const int bS  = blockIdx.z;
    const int gx0 = blockIdx.x * 64;
    const int gy0 = blockIdx.y * 8;

    // ---- stage A: gmem -> (hi,lo) bf16 pair records ----
    for (int u = tid; u < (CINP / 2) * NREC; u += 256) {
        int rec = u % NREC;
        int cp  = u / NREC;                  // channel pair
        int x   = rec % TXW;
        int y   = rec / TXW;
        int gy = gy0 - 1 + y, gx = gx0 - 1 + x;
        float f0 = 0.f, f1 = 0.f;
        bool ok = ((unsigned)gy < HW) && ((unsigned)gx < HW) && (2 * cp < CIN);
        if (PIN) {
            const float* inb = (const float*)in + (size_t)bS * in_sz * IMG;
            if (ok) {
                f0 = inb[(size_t)(2 * cp) * IMG + gy * HW + gx];
                if (2 * cp + 1 < CIN) f1 = inb[(size_t)(2 * cp + 1) * IMG + gy * HW + gx];
            }
        } else {
            const float2* inb2 = (const float2*)in + (size_t)bS * in_sz * IMG;
            if (ok) {
                float2 v = inb2[(size_t)cp * IMG + gy * HW + gx];
                f0 = v.x; f1 = v.y;
            }
        }
        unsigned hi, lo; split2(f0, f1, hi, lo);
        s_a[rec * RSW + cp]       = hi;
        s_a[rec * RSW + CHW + cp] = lo;
    }

    // ---- prep B (k16 chunk, channels 0..15): fragment order ----
    const float* wsrc = wflat + (size_t)bS * wP + wbase;
    for (int s = tid; s < NBK * 9 * 32; s += 256) {
        int lane = s & 31;
        int r  = s >> 5;
        int sh = r % 9;
        int nb = r / 9;
        int o  = nb * 8 + (lane >> 2);       // n = g
        int t4 = (lane & 3) * 2;             // k = t4, t4+1 (b0); t4+8.. (b1)
        float w00 = 0.f, w01 = 0.f, w10 = 0.f, w11 = 0.f;
        if (o < COUT) {
            const float* wr = wsrc + (size_t)o * CIN * 9 + sh;
            if (t4     < CIN) w00 = wr[(t4    ) * 9];
            if (t4 + 1 < CIN) w01 = wr[(t4 + 1) * 9];
            if (t4 + 8 < CIN) w10 = wr[(t4 + 8) * 9];
            if (t4 + 9 < CIN) w11 = wr[(t4 + 9) * 9];
        }
        unsigned b0h, b0l, b1h, b1l;
        split2(w00, w01, b0h, b0l);
        split2(w10, w11, b1h, b1l);
        s_b16[s] = make_uint4(b0h, b1h, b0l, b1l);
    }
    // ---- prep B (k8 tail, channels 16..23) ----
    if (KC8) {
        for (int s = tid; s < NBK * 9 * 32; s += 256) {
            int lane = s & 31;
            int r  = s >> 5;
            int sh = r % 9;
            int nb = r / 9;
            int o  = nb * 8 + (lane >> 2);
            int i0 = 16 + (lane & 3) * 2;
            float w0 = 0.f, w1 = 0.f;
            if (o < COUT) {
                const float* wr = wsrc + (size_t)o * CIN * 9 + sh;
                if (i0     < CIN) w0 = wr[(i0    ) * 9];
                if (i0 + 1 < CIN) w1 = wr[(i0 + 1) * 9];
            }
            unsigned hi, lo; split2(w0, w1, hi, lo);
            s_b8[s] = make_uint2(hi, lo);
        }
    }
    if (tid < COUTP) {
        float sc = 0.f, bi = 0.f;
        if (tid < COUT) {
            int c = bnoff + tid;
            float inv = gam[c] * rsqrtf(varr[c] + 1e-5f);
            sc = inv; bi = bet[c] - mea[c] * inv;
        }
        s_sc[tid] = sc; s_bi[tid] = bi;
    }
    __syncthreads();

    const int lane = tid & 31, warp = tid >> 5;
    const int g = lane >> 2, t = lane & 3;
    const int xseg = warp & 3;               // 16-px segment
    const int y0   = (warp >> 2) * 4;        // 4 output rows per warp

    // ldmatrix lane->address offsets (words), constant per thread
    const int rowoff = ((lane >> 3) & 1) * 8 + (lane & 7);
    const int offA16 = rowoff * RSW + (lane >> 4) * 4;        // k16: words 0-3 / 4-7
    const int offA8  = rowoff * RSW + 8 + (lane >> 4) * CHW;  // k8: word 8, hi/lo split
    const unsigned sa_base = (unsigned)__cvta_generic_to_shared(s_a);

    float acc[4][NBK][4];
    #pragma unroll
    for (int m = 0; m < 4; m++)
        #pragma unroll
        for (int nb = 0; nb < NBK; nb++)
            #pragma unroll
            for (int i = 0; i < 4; i++) acc[m][nb][i] = 0.f;

    #pragma unroll
    for (int kx = 0; kx < 3; kx++) {
        const int rec0 = y0 * TXW + xseg * 16 + kx;   // input record, row-idx 0

        // ---- pass hi: A_hi rows, terms hh + hl ----
        unsigned A[6][4];
        #pragma unroll
        for (int rr = 0; rr < 6; rr++)
            ldsm4(A[rr], sa_base + ((rec0 + rr * TXW) * RSW + offA16) * 4);
        #pragma unroll
        for (int ky = 0; ky < 3; ky++)
            #pragma unroll
            for (int nb = 0; nb < NBK; nb++) {
                const uint4 B = s_b16[(nb * 9 + ky * 3 + kx) * 32 + lane];
                #pragma unroll
                for (int m = 0; m < 4; m++) mma16(acc[m][nb], A[m + ky], B.x, B.y);
                #pragma unroll
                for (int m = 0; m < 4; m++) mma16(acc[m][nb], A[m + ky], B.z, B.w);
            }

        // ---- pass lo: A_lo rows, term lh ----
        #pragma unroll
        for (int rr = 0; rr < 6; rr++)
            ldsm4(A[rr], sa_base + ((rec0 + rr * TXW) * RSW + offA16 + CHW) * 4);
        #pragma unroll
        for (int ky = 0; ky < 3; ky++)
            #pragma unroll
            for (int nb = 0; nb < NBK; nb++) {
                const uint2 Bh = *(const uint2*)&s_b16[(nb * 9 + ky * 3 + kx) * 32 + lane];
                #pragma unroll
                for (int m = 0; m < 4; m++) mma16(acc[m][nb], A[m + ky], Bh.x, Bh.y);
            }

        // ---- k8 tail (channels 16..23): hi+lo in one ldmatrix ----
        if (KC8) {
            unsigned A8[6][4];               // [0,1]=hi a0,a1; [2,3]=lo a0,a1
            #pragma unroll
            for (int rr = 0; rr < 6; rr++)
                ldsm4(A8[rr], sa_base + ((rec0 + rr * TXW) * RSW + offA8) * 4);
            #pragma unroll
            for (int ky = 0; ky < 3; ky++)
                #pragma unroll
                for (int nb = 0; nb < NBK; nb++) {
                    const uint2 B = s_b8[(nb * 9 + ky * 3 + kx) * 32 + lane];
                    #pragma unroll
                    for (int m = 0; m < 4; m++) mma8(acc[m][nb], A8[m+ky][0], A8[m+ky][1], B.x);
                    #pragma unroll
                    for (int m = 0; m < 4; m++) mma8(acc[m][nb], A8[m+ky][0], A8[m+ky][1], B.y);
                    #pragma unroll
                    for (int m = 0; m < 4; m++) mma8(acc[m][nb], A8[m+ky][2], A8[m+ky][3], B.x);
                }
        }
    }

    // ---- epilogue: BN (eval) + ReLU, pair-interleaved STG.64 ----
    float2* ob2 = out + (size_t)bS * out_pairs * IMG;
    #pragma unroll
    for (int nb = 0; nb < NBK; nb++) {
        const int o0 = nb * 8 + 2 * t, o1 = o0 + 1;
        const int pr = nb * 4 + t;           // pair index
        if (o0 < COUT) {
            const float sc0 = s_sc[o0], bi0 = s_bi[o0];
            const float sc1 = s_sc[o1], bi1 = s_bi[o1];
            #pragma unroll
            for (int m = 0; m < 4; m++) {
                const int y = gy0 + y0 + m;
                const int x = gx0 + xseg * 16 + g;
                float2* p = ob2 + (size_t)pr * IMG + y * HW + x;
                p[0] = make_float2(fmaxf(fmaf(acc[m][nb][0], sc0, bi0), 0.f),
                                   fmaxf(fmaf(acc[m][nb][1], sc1, bi1), 0.f));
                p[8] = make_float2(fmaxf(fmaf(acc[m][nb][2], sc0, bi0), 0.f),
                                   fmaxf(fmaf(acc[m][nb][3], sc1, bi1), 0.f));
            }
        }
    }
}

// ---------------------------------------------------------------------------
// Copy planar x (10 ch) into pairs 6..10 of bufA (dense-skip concat source).
// ---------------------------------------------------------------------------
__global__ void copy_x_kernel(const float* __restrict__ x, float2* __restrict__ bufA)
{
    size_t idx = (size_t)blockIdx.x * blockDim.x + threadIdx.x;
    const size_t total = (size_t)BATCH * 5 * IMG;
    if (idx < total) {
        int p  = (int)(idx % IMG);
        int cp = (int)((idx / IMG) % 5);
        int b  = (int)(idx / ((size_t)IMG * 5));
        float f0 = x[((size_t)b * 10 + 2 * cp) * IMG + p];
        float f1 = x[((size_t)b * 10 + 2 * cp + 1) * IMG + p];
        bufA[((size_t)b * 11 + 6 + cp) * IMG + p] = make_float2(f0, f1);
    }
}

// ---------------------------------------------------------------------------
// Final per-sample 1x1 conv: bufA (11 pairs, interleaved) -> planar [B,11,H,W]
// ---------------------------------------------------------------------------
__global__ __launch_bounds__(256)
void conv1x1_kernel(const float2* __restrict__ in, const float* __restrict__ w4,
                    float* __restrict__ out)
{
    __shared__ float s_w[11 * 22];
    const int b   = blockIdx.y;
    const int tid = threadIdx.x;
    if (tid < 242) s_w[tid] = w4[b * 242 + tid];
    __syncthreads();

    const int p0 = blockIdx.x * (256 * 4) + tid;
    const float2* inb = in  + (size_t)b * 11 * IMG;
    float*        ob  = out + (size_t)b * 11 * IMG;

    float acc[4][11];
    #pragma unroll
    for (int q = 0; q < 4; q++)
        #pragma unroll
        for (int o = 0; o < 11; o++) acc[q][o] = 0.f;

    #pragma unroll 2
    for (int pr = 0; pr < 11; pr++) {
        float2 v[4];
        #pragma unroll
        for (int q = 0; q < 4; q++) v[q] = inb[(size_t)pr * IMG + p0 + q * 256];
        #pragma unroll
        for (int o = 0; o < 11; o++) {
            float w0 = s_w[o * 22 + 2 * pr];
            float w1 = s_w[o * 22 + 2 * pr + 1];
            #pragma unroll
            for (int q = 0; q < 4; q++) {
                acc[q][o] = fmaf(v[q].x, w0, acc[q][o]);
                acc[q][o] = fmaf(v[q].y, w1, acc[q][o]);
            }
        }
    }
    #pragma unroll
    for (int o = 0; o < 11; o++)
        #pragma unroll
        for (int q = 0; q < 4; q++)
            ob[(size_t)o * IMG + p0 + q * 256] = acc[q][o];
}

// ---------------------------------------------------------------------------

static int smem_bytes_mma(int cinp, int coutp) {
    int nbk = coutp / 8;
    int rsw = (cinp == 16) ? 20 : 28;
    int b16 = nbk * 9 * 32 * 16;
    int b8  = (cinp == 24) ? nbk * 9 * 32 * 8 : 0;
    return 660 * rsw * 4 + b16 + b8 + 2 * coutp * 4;
}

extern "C" void kernel_launch(void* const* d_in, const int* in_sizes, int n_in,
                              void* d_out, int out_size)
{
    const float* x   = (const float*)d_in[0];
    const float* w1  = (const float*)d_in[1];
    const float* w2  = (const float*)d_in[2];
    const float* w3  = (const float*)d_in[3];
    const float* w4  = (const float*)d_in[4];
    const float* gam = (const float*)d_in[5];
    const float* bet = (const float*)d_in[6];
    const float* mea = (const float*)d_in[7];
    const float* var = (const float*)d_in[8];
    float* out = (float*)d_out;

    float2 *bufA, *bufB, *bufC;
    cudaGetSymbolAddress((void**)&bufA, g_bufA);
    cudaGetSymbolAddress((void**)&bufB, g_bufB);
    cudaGetSymbolAddress((void**)&bufC, g_bufC);

    // opt-in to >48KB dynamic smem (idempotent; host-side, capture-safe)
    cudaFuncSetAttribute((const void*)conv3x3_mma<10,16,12,16,true>,  cudaFuncAttributeMaxDynamicSharedMemorySize, smem_bytes_mma(16,16));
    cudaFuncSetAttribute((const void*)conv3x3_mma<12,16,12,16,false>, cudaFuncAttributeMaxDynamicSharedMemorySize, smem_bytes_mma(16,16));
    cudaFuncSetAttribute((const void*)conv3x3_mma<22,24,24,24,false>, cudaFuncAttributeMaxDynamicSharedMemorySize, smem_bytes_mma(24,24));
    cudaFuncSetAttribute((const void*)conv3x3_mma<24,24,24,24,false>, cudaFuncAttributeMaxDynamicSharedMemorySize, smem_bytes_mma(24,24));
    cudaFuncSetAttribute((const void*)conv3x3_mma<24,24,12,16,false>, cudaFuncAttributeMaxDynamicSharedMemorySize, smem_bytes_mma(24,16));

    const dim3 grd(2, 16, BATCH);   // 64x8 pixel tiles

    // x -> bufA pairs 6..10 (skip-concat source, written once per launch)
    copy_x_kernel<<<(BATCH * 5 * IMG + 255) / 256, 256>>>(x, bufA);

    // ---- stage 1 ----  (BN offsets: 0,12,24)
    conv3x3_mma<10,16,12,16,true ><<<grd, 256, smem_bytes_mma(16,16)>>>(x,    10, w1, 3672,    0, gam,bet,mea,var,   0, bufB, 12);
    conv3x3_mma<12,16,12,16,false><<<grd, 256, smem_bytes_mma(16,16)>>>(bufB, 12, w1, 3672, 1080, gam,bet,mea,var,  12, bufC, 12);
    conv3x3_mma<12,16,12,16,false><<<grd, 256, smem_bytes_mma(16,16)>>>(bufC, 12, w1, 3672, 2376, gam,bet,mea,var,  24, bufA, 11);
    // ---- stage 2 ----  (BN offsets: 36,60,84)
    conv3x3_mma<22,24,24,24,false><<<grd, 256, smem_bytes_mma(24,24)>>>(bufA, 11, w2, 12528,    0, gam,bet,mea,var,  36, bufB, 12);
    conv3x3_mma<24,24,24,24,false><<<grd, 256, smem_bytes_mma(24,24)>>>(bufB, 12, w2, 12528, 4752, gam,bet,mea,var,  60, bufC, 12);
    conv3x3_mma<24,24,12,16,false><<<grd, 256, smem_bytes_mma(24,16)>>>(bufC, 12, w2, 12528, 9936, gam,bet,mea,var,  84, bufA, 11);
    // ---- stage 3 ----  (BN offsets: 96,120,144)
    conv3x3_mma<22,24,24,24,false><<<grd, 256, smem_bytes_mma(24,24)>>>(bufA, 11, w3, 12528,    0, gam,bet,mea,var,  96, bufB, 12);
    conv3x3_mma<24,24,24,24,false><<<grd, 256, smem_bytes_mma(24,24)>>>(bufB, 12, w3, 12528, 4752, gam,bet,mea,var, 120, bufC, 12);
    conv3x3_mma<24,24,12,16,false><<<grd, 256, smem_bytes_mma(24,16)>>>(bufC, 12, w3, 12528, 9936, gam,bet,mea,var, 144, bufA, 11);
    // ---- stage 4: 1x1 predictor ----
    conv1x1_kernel<<<dim3(IMG / (256 * 4), BATCH), 256>>>(bufA, w4, out);
}